// round 3
// baseline (speedup 1.0000x reference)
#include <cuda_runtime.h>
#include <math.h>
#include <stdint.h>

typedef unsigned long long ull;

// ---------------- constants ----------------
#define TT    24          // timesteps per CTA tile (240/24 = 10 tiles)
#define XSTR  28          // smem row stride for [180][TT] tiles
#define KC    12          // K-chunk staged in smem (180 = 15 * 12)
#define NCH   15
#define HPAD  192         // padded h-slots per k row in smem weight tiles
#define THR1  192         // 3 t-groups x 64 h-lanes

// smem layout (bytes)
#define SMEM_XS   0
#define SMEM_HS   20160                      // 180*28*4
#define SMEM_WS4  40320                      // + 180*28*4
#define SMEM_WS2  77184                      // + KC*192*4*4 = 36864
#define SMEM_RA   95616                      // + KC*192*2*4 = 18432
#define SMEM_RM   96384                      // + 8*24*4
#define SMEM_RS   96480
#define SMEM1_TOTAL 96576

// ---------------- device scratch (static allocation only) ----------------
__device__ float g_Wenc4[180 * 180 * 4];     // [k][h][{i,i,g,g}]
__device__ float g_Wenc2[180 * 180 * 2];     // [k][h][{o,o}]
__device__ float g_Wdec4[180 * 180 * 4];
__device__ float g_Wdec2[180 * 180 * 2];
__device__ float g_bencP[180 * 4];           // [h][{i,g,o,pad}]
__device__ float g_bdecP[180 * 4];
__device__ float g_hdec[88473600];           // [2048][240][180]
__device__ float g_part[16 * 2048 * 40];     // split-K partial logits

// ---------------- f32x2 helpers ----------------
__device__ __forceinline__ ull ffma2(ull a, ull b, ull c) {
    ull d;
    asm("fma.rn.f32x2 %0, %1, %2, %3;" : "=l"(d) : "l"(a), "l"(b), "l"(c));
    return d;
}
__device__ __forceinline__ float2 unpackf2(ull v) {
    float2 r;
    asm("mov.b64 {%0, %1}, %2;" : "=f"(r.x), "=f"(r.y) : "l"(v));
    return r;
}
__device__ __forceinline__ float sigmoidf_(float v) { return 1.f / (1.f + expf(-v)); }

// ---------------- kernel P: repack weights k-major, pre-duplicated pairs ----------------
__global__ void pack_weights(const float* __restrict__ We, const float* __restrict__ bie,
                             const float* __restrict__ bhe, const float* __restrict__ Wd,
                             const float* __restrict__ bid, const float* __restrict__ bhd) {
    int idx = blockIdx.x * blockDim.x + threadIdx.x;
    int stride = gridDim.x * blockDim.x;
    for (int i = idx; i < 180 * 180; i += stride) {
        int k = i / 180, h = i % 180;
        float ei = We[h * 180 + k];
        float eg = We[(360 + h) * 180 + k];
        float eo = We[(540 + h) * 180 + k];
        float di = Wd[h * 180 + k];
        float dg = Wd[(360 + h) * 180 + k];
        float dof = Wd[(540 + h) * 180 + k];
        *(float4*)&g_Wenc4[(size_t)i * 4] = make_float4(ei, ei, eg, eg);
        *(float2*)&g_Wenc2[(size_t)i * 2] = make_float2(eo, eo);
        *(float4*)&g_Wdec4[(size_t)i * 4] = make_float4(di, di, dg, dg);
        *(float2*)&g_Wdec2[(size_t)i * 2] = make_float2(dof, dof);
    }
    for (int h = idx; h < 180; h += stride) {
        g_bencP[h * 4 + 0] = bie[h] + bhe[h];
        g_bencP[h * 4 + 1] = bie[360 + h] + bhe[360 + h];
        g_bencP[h * 4 + 2] = bie[540 + h] + bhe[540 + h];
        g_bencP[h * 4 + 3] = 0.f;
        g_bdecP[h * 4 + 0] = bid[h] + bhd[h];
        g_bdecP[h * 4 + 1] = bid[360 + h] + bhd[360 + h];
        g_bdecP[h * 4 + 2] = bid[540 + h] + bhd[540 + h];
        g_bdecP[h * 4 + 3] = 0.f;
    }
}

// ---------------- kernel 1: fused enc-GEMM -> softmax -> dec-GEMM -> hdec ----------------
__global__ void __launch_bounds__(THR1, 2) fused_encdec(const float* __restrict__ x) {
    extern __shared__ char smem_raw[];
    float(*Xs)[XSTR] = reinterpret_cast<float(*)[XSTR]>(smem_raw + SMEM_XS);
    float(*Hs)[XSTR] = reinterpret_cast<float(*)[XSTR]>(smem_raw + SMEM_HS);
    float* Ws4 = reinterpret_cast<float*>(smem_raw + SMEM_WS4);   // [KC][HPAD][4]
    float* Ws2 = reinterpret_cast<float*>(smem_raw + SMEM_WS2);   // [KC][HPAD][2]
    float(*redA)[24] = reinterpret_cast<float(*)[24]>(smem_raw + SMEM_RA);
    float* redM = reinterpret_cast<float*>(smem_raw + SMEM_RM);
    float* redS = reinterpret_cast<float*>(smem_raw + SMEM_RS);

    const int b  = blockIdx.y;
    const int t0 = blockIdx.x * TT;
    const int tid = threadIdx.x;
    const int tx = tid / 64;   // 0..2 : t-group of 8 timesteps
    const int ty = tid % 64;   // h lanes

    // load input tile: Xs[f][t] = x[b][f][t0+t]   (x is [B,180,240] contiguous)
    for (int i = tid; i < 180 * TT; i += THR1) {
        int f = i / TT, t = i % TT;
        Xs[f][t] = x[((size_t)b * 180 + f) * 240 + t0 + t];
    }

    for (int pass = 0; pass < 2; pass++) {
        const float* W4g = pass ? g_Wdec4 : g_Wenc4;
        const float* W2g = pass ? g_Wdec2 : g_Wenc2;
        ull acc[3][3][4];
#pragma unroll
        for (int j = 0; j < 3; j++)
#pragma unroll
            for (int g = 0; g < 3; g++)
#pragma unroll
                for (int v = 0; v < 4; v++) acc[j][g][v] = 0ull;

        for (int c = 0; c < NCH; c++) {
            __syncthreads();  // protect Ws reuse; also orders Xs producers
            // stage W chunk into padded smem rows
            {
                const float4* src4 = (const float4*)(W4g + (size_t)c * KC * 720);
                for (int i = tid; i < KC * 180; i += THR1) {
                    int kk = i / 180, h = i % 180;
                    *(float4*)&Ws4[(kk * HPAD + h) * 4] = src4[i];
                }
                const float4* src2 = (const float4*)(W2g + (size_t)c * KC * 360);
                for (int i = tid; i < KC * 90; i += THR1) {
                    int kk = i / 90, h2 = i % 90;
                    *(float4*)&Ws2[(kk * HPAD + h2 * 2) * 2] = src2[i];
                }
            }
            __syncthreads();
#pragma unroll 4
            for (int kk = 0; kk < KC; kk++) {
                const int k = c * KC + kk;
                ulonglong2 xa = *(const ulonglong2*)&Xs[k][tx * 8];
                ulonglong2 xb = *(const ulonglong2*)&Xs[k][tx * 8 + 4];
                ull xs0 = xa.x, xs1 = xa.y, xs2 = xb.x, xs3 = xb.y;
#pragma unroll
                for (int j = 0; j < 3; j++) {
                    const int h = ty + 64 * j;
                    ulonglong2 wig = *(const ulonglong2*)&Ws4[(kk * HPAD + h) * 4];
                    ull wo = *(const ull*)&Ws2[(kk * HPAD + h) * 2];
                    ull wi = wig.x, wg = wig.y;
                    acc[j][0][0] = ffma2(xs0, wi, acc[j][0][0]);
                    acc[j][0][1] = ffma2(xs1, wi, acc[j][0][1]);
                    acc[j][0][2] = ffma2(xs2, wi, acc[j][0][2]);
                    acc[j][0][3] = ffma2(xs3, wi, acc[j][0][3]);
                    acc[j][1][0] = ffma2(xs0, wg, acc[j][1][0]);
                    acc[j][1][1] = ffma2(xs1, wg, acc[j][1][1]);
                    acc[j][1][2] = ffma2(xs2, wg, acc[j][1][2]);
                    acc[j][1][3] = ffma2(xs3, wg, acc[j][1][3]);
                    acc[j][2][0] = ffma2(xs0, wo, acc[j][2][0]);
                    acc[j][2][1] = ffma2(xs1, wo, acc[j][2][1]);
                    acc[j][2][2] = ffma2(xs2, wo, acc[j][2][2]);
                    acc[j][2][3] = ffma2(xs3, wo, acc[j][2][3]);
                }
            }
        }

        // activations: c = sig(i)*tanh(g); h = sig(o)*tanh(c)
        const float* bp = pass ? g_bdecP : g_bencP;
#pragma unroll
        for (int j = 0; j < 3; j++) {
            int h = ty + 64 * j;
            if (h < 180) {
                float4 bb = *(const float4*)&bp[h * 4];
#pragma unroll
                for (int v = 0; v < 4; v++) {
                    float2 fi = unpackf2(acc[j][0][v]);
                    float2 fg = unpackf2(acc[j][1][v]);
                    float2 fo = unpackf2(acc[j][2][v]);
                    float c0 = sigmoidf_(fi.x + bb.x) * tanhf(fg.x + bb.y);
                    float c1 = sigmoidf_(fi.y + bb.x) * tanhf(fg.y + bb.y);
                    float h0 = sigmoidf_(fo.x + bb.z) * tanhf(c0);
                    float h1 = sigmoidf_(fo.y + bb.z) * tanhf(c1);
                    Hs[h][tx * 8 + 2 * v]     = h0;
                    Hs[h][tx * 8 + 2 * v + 1] = h1;
                }
            }
        }
        __syncthreads();

        if (pass == 0) {
            // softmax over h (180) per column t, result -> Xs (decoder input)
            int col = tid % 24, sl = tid / 24;            // 24 cols x 8 slices
            int h0 = sl * 23, h1 = min(180, h0 + 23);
            float m = -1e30f;
            for (int h = h0; h < h1; h++) m = fmaxf(m, Hs[h][col]);
            redA[sl][col] = m;
            __syncthreads();
            if (sl == 0) {
                float mm = redA[0][col];
#pragma unroll
                for (int s = 1; s < 8; s++) mm = fmaxf(mm, redA[s][col]);
                redM[col] = mm;
            }
            __syncthreads();
            float mm = redM[col];
            float s = 0.f;
            for (int h = h0; h < h1; h++) {
                float e = expf(Hs[h][col] - mm);
                Hs[h][col] = e;                 // cache exp; each (sl,col) owns range
                s += e;
            }
            redA[sl][col] = s;
            __syncthreads();
            if (sl == 0) {
                float ss = 0.f;
#pragma unroll
                for (int s2 = 0; s2 < 8; s2++) ss += redA[s2][col];
                redS[col] = 1.f / ss;
            }
            __syncthreads();
            float inv = redS[col];
            for (int h = h0; h < h1; h++) Xs[h][col] = Hs[h][col] * inv;
            // next pass's first __syncthreads() orders these writes vs readers
        } else {
            // write h_dec: g_hdec[b][t0+t][h]
            for (int i = tid; i < 180 * TT; i += THR1) {
                int h = i % 180, t = i / 180;
                g_hdec[((size_t)b * 240 + t0 + t) * 180 + h] = Hs[h][t];
            }
        }
    }
}

// ---------------- kernel C: output GEMM, split-K partials ----------------
__global__ void __launch_bounds__(256) out_gemm(const float* __restrict__ Wout) {
    __shared__ float Hc[64][62];
    __shared__ float Wc[40][62];
    const int ks = blockIdx.x;        // 0..15
    const int b0 = blockIdx.y * 64;   // 0..31 tiles
    const int k0 = ks * 2700;
    const int tid = threadIdx.x;
    const int bg = tid % 32;
    const int ng = tid / 32;          // 0..7 -> 5 n each

    ull acc2[2][5];
#pragma unroll
    for (int bi = 0; bi < 2; bi++)
#pragma unroll
        for (int q = 0; q < 5; q++) acc2[bi][q] = 0ull;

    for (int c = 0; c < 45; c++) {
        __syncthreads();
        const int kb = k0 + c * 60;
        for (int i = tid; i < 64 * 60; i += 256) {
            int bb = i / 60, k = i % 60;
            Hc[bb][k] = g_hdec[(size_t)(b0 + bb) * 43200 + kb + k];
        }
        for (int i = tid; i < 40 * 60; i += 256) {
            int n = i / 60, k = i % 60;
            Wc[n][k] = Wout[(size_t)n * 43200 + kb + k];
        }
        __syncthreads();
#pragma unroll 6
        for (int kp = 0; kp < 30; kp++) {
            ull h0 = *(const ull*)&Hc[bg][kp * 2];
            ull h1 = *(const ull*)&Hc[bg + 32][kp * 2];
#pragma unroll
            for (int q = 0; q < 5; q++) {
                ull w = *(const ull*)&Wc[ng * 5 + q][kp * 2];
                acc2[0][q] = ffma2(h0, w, acc2[0][q]);
                acc2[1][q] = ffma2(h1, w, acc2[1][q]);
            }
        }
    }
#pragma unroll
    for (int bi = 0; bi < 2; bi++)
#pragma unroll
        for (int q = 0; q < 5; q++) {
            float2 p = unpackf2(acc2[bi][q]);
            g_part[((size_t)ks * 2048 + b0 + bg + 32 * bi) * 40 + ng * 5 + q] = p.x + p.y;
        }
}

// ---------------- kernel D: reduce split-K + bias + grouped softmax ----------------
__global__ void reduce_softmax(const float* __restrict__ bout, float* __restrict__ out) {
    __shared__ float sm[40];
    const int b = blockIdx.x;
    const int n = threadIdx.x;  // 0..39
    float l = bout[n];
#pragma unroll
    for (int ks = 0; ks < 16; ks++) l += g_part[((size_t)ks * 2048 + b) * 40 + n];
    sm[n] = l;
    __syncthreads();
    const int g0 = (n / 10) * 10;
    float m = sm[g0];
#pragma unroll
    for (int i = 1; i < 10; i++) m = fmaxf(m, sm[g0 + i]);
    float s = 0.f;
#pragma unroll
    for (int i = 0; i < 10; i++) s += expf(sm[g0 + i] - m);
    out[(size_t)b * 40 + n] = expf(l - m) / s;
}

// ---------------- launcher ----------------
extern "C" void kernel_launch(void* const* d_in, const int* in_sizes, int n_in,
                              void* d_out, int out_size) {
    const float* x    = (const float*)d_in[0];
    const float* Wenc = (const float*)d_in[1];
    const float* bie  = (const float*)d_in[2];
    const float* bhe  = (const float*)d_in[3];
    const float* Wdec = (const float*)d_in[4];
    const float* bid  = (const float*)d_in[5];
    const float* bhd  = (const float*)d_in[6];
    const float* Wout = (const float*)d_in[7];
    const float* bout = (const float*)d_in[8];
    float* out = (float*)d_out;

    cudaFuncSetAttribute(fused_encdec, cudaFuncAttributeMaxDynamicSharedMemorySize, SMEM1_TOTAL);

    pack_weights<<<128, 256>>>(Wenc, bie, bhe, Wdec, bid, bhd);
    fused_encdec<<<dim3(10, 2048), THR1, SMEM1_TOTAL>>>(x);
    out_gemm<<<dim3(16, 32), 256>>>(Wout);
    reduce_softmax<<<2048, 40>>>(bout, out);
}